// round 7
// baseline (speedup 1.0000x reference)
#include <cuda_runtime.h>
#include <cuda_bf16.h>
#include <math.h>
#include <stdint.h>

#define B_   8
#define S_   4096
#define D_   256
#define SEG_ 128
#define E_   32
#define MASKVAL (-3.402823466e38f)

#define SEQ_ST 264   // halves
#define WB_ST  24    // halves

// smem byte offsets
#define OFF_SEQ_H 0                    // 128*264*2 = 67584
#define OFF_SEQ_L 67584
#define OFF_WBUF  135168               // 2 bufs x (12288 hi + 12288 lo) = 49152
#define OFF_BIAS  184320               // 1024
#define OFF_POOL  185344               // 8*256*4 = 8192
#define SMEM_TOT  193536

// w pre-packed per 16-wide k-chunk: [kc][m][kk], hi and lo bf16 splits
__device__ __nv_bfloat16 g_wh[16*256*16];
__device__ __nv_bfloat16 g_wl[16*256*16];
__device__ int g_fix[E_];

// ---------------------------------------------------------------------------
__global__ void prep_kernel(const float* __restrict__ w) {
    int idx = blockIdx.x * 256 + threadIdx.x;   // 65536
    int m = idx >> 8, d = idx & 255;
    float v = w[idx];
    __nv_bfloat16 h = __float2bfloat16(v);
    __nv_bfloat16 l = __float2bfloat16(v - __bfloat162float(h));
    int kc = d >> 4, kk = d & 15;
    int o = (kc * 256 + m) * 16 + kk;
    g_wh[o] = h; g_wl[o] = l;
    if (idx < E_) g_fix[idx] = 0;
}

// ---------------------------------------------------------------------------
__global__ void fix_kernel(const float* __restrict__ mask) {
    int e = blockIdx.x;
    int warp = threadIdx.x >> 5, lane = threadIdx.x & 31;
    int found = 0;
    for (int r = warp; r < B_ * SEG_; r += 8) {
        int b = r >> 7, l = r & 127;
        const float* row = mask + ((size_t)b * S_ + (size_t)e * SEG_ + l) * S_
                                + (size_t)e * SEG_;
        int allm = 1;
        #pragma unroll
        for (int k = 0; k < 4; k++)
            if (row[lane + 32 * k] != MASKVAL) allm = 0;
        if (__all_sync(0xffffffffu, allm)) { found = 1; break; }
    }
    if (found && lane == 0) atomicOr(&g_fix[e], 1);
}

// ---------------------------------------------------------------------------
__device__ __forceinline__ void ldsm4(unsigned a, unsigned& r0, unsigned& r1,
                                      unsigned& r2, unsigned& r3) {
    asm volatile("ldmatrix.sync.aligned.m8n8.x4.shared.b16 {%0,%1,%2,%3},[%4];"
                 : "=r"(r0), "=r"(r1), "=r"(r2), "=r"(r3) : "r"(a));
}
__device__ __forceinline__ void ldsm4t(unsigned a, unsigned& r0, unsigned& r1,
                                       unsigned& r2, unsigned& r3) {
    asm volatile("ldmatrix.sync.aligned.m8n8.x4.trans.shared.b16 {%0,%1,%2,%3},[%4];"
                 : "=r"(r0), "=r"(r1), "=r"(r2), "=r"(r3) : "r"(a));
}
__device__ __forceinline__ void mma16816(float* c, unsigned a0, unsigned a1,
                                         unsigned a2, unsigned a3,
                                         unsigned b0, unsigned b1) {
    asm volatile(
        "mma.sync.aligned.m16n8k16.row.col.f32.bf16.bf16.f32 "
        "{%0,%1,%2,%3},{%4,%5,%6,%7},{%8,%9},{%0,%1,%2,%3};"
        : "+f"(c[0]), "+f"(c[1]), "+f"(c[2]), "+f"(c[3])
        : "r"(a0), "r"(a1), "r"(a2), "r"(a3), "r"(b0), "r"(b1));
}
__device__ __forceinline__ unsigned packhi(float a, float b) {
    __nv_bfloat162 p;
    p.x = __float2bfloat16(a); p.y = __float2bfloat16(b);
    return *(unsigned*)&p;
}
__device__ __forceinline__ unsigned packlo(float a, float b, unsigned hi) {
    __nv_bfloat162 h = *(__nv_bfloat162*)&hi;
    __nv_bfloat162 p;
    p.x = __float2bfloat16(a - __bfloat162float(h.x));
    p.y = __float2bfloat16(b - __bfloat162float(h.y));
    return *(unsigned*)&p;
}

// ---------------------------------------------------------------------------
__global__ void __launch_bounds__(256, 1)
main_kernel(const float* __restrict__ hidden,
            const float* __restrict__ maskp,
            const float* __restrict__ bvec,
            float* __restrict__ out)
{
    extern __shared__ char smc[];
    const unsigned sb = (unsigned)__cvta_generic_to_shared(smc);

    __nv_bfloat16* seqh = (__nv_bfloat16*)(smc + OFF_SEQ_H);
    __nv_bfloat16* seql = (__nv_bfloat16*)(smc + OFF_SEQ_L);
    float* bias = (float*)(smc + OFF_BIAS);
    float* pool = (float*)(smc + OFF_POOL);

    const int t = threadIdx.x;
    const int lane = t & 31, wi = t >> 5;
    const int rg = lane >> 2, tg = lane & 3;
    const int e = blockIdx.x, bb = blockIdx.y;

    // ---- load seq tile, split bf16 hi/lo, row-major stride 264 ----
    const float* seq_g = hidden + ((size_t)bb * S_ + (size_t)e * SEG_) * D_;
    for (int i = t; i < SEG_ * D_ / 4; i += 256) {
        int l = i >> 6, d = (i & 63) << 2;
        float4 v = *(const float4*)(seq_g + l * D_ + d);
        __nv_bfloat162 h0, h1, l0, l1;
        h0.x = __float2bfloat16(v.x); h0.y = __float2bfloat16(v.y);
        h1.x = __float2bfloat16(v.z); h1.y = __float2bfloat16(v.w);
        l0.x = __float2bfloat16(v.x - __bfloat162float(h0.x));
        l0.y = __float2bfloat16(v.y - __bfloat162float(h0.y));
        l1.x = __float2bfloat16(v.z - __bfloat162float(h1.x));
        l1.y = __float2bfloat16(v.w - __bfloat162float(h1.y));
        *(__nv_bfloat162*)(seqh + l * SEQ_ST + d)     = h0;
        *(__nv_bfloat162*)(seqh + l * SEQ_ST + d + 2) = h1;
        *(__nv_bfloat162*)(seql + l * SEQ_ST + d)     = l0;
        *(__nv_bfloat162*)(seql + l * SEQ_ST + d + 2) = l1;
    }
    bias[t] = bvec[t];
    const int fixe = g_fix[e];

    // ---- store w chunk 0 into buf0 (thread t = m-row t) ----
    {
        const uint4* gh = (const uint4*)(g_wh) + t * 2;
        const uint4* gl = (const uint4*)(g_wl) + t * 2;
        uint4 a0 = gh[0], a1 = gh[1], c0 = gl[0], c1 = gl[1];
        char* bh = smc + OFF_WBUF + t * 48;
        char* bl = smc + OFF_WBUF + 12288 + t * 48;
        *(uint4*)bh = a0; *(uint4*)(bh + 16) = a1;
        *(uint4*)bl = c0; *(uint4*)(bl + 16) = c1;
    }
    __syncthreads();

    // ldmatrix address helpers (round-3-validated maps)
    auto adrA = [&](unsigned off, int st, int r0, int k0) -> unsigned {
        int r = r0 + (lane & 7) + ((lane >> 3) & 1) * 8;
        int c = k0 + ((lane >> 4) & 1) * 8;
        return sb + off + (unsigned)((r * st + c) * 2);
    };
    auto adrB = [&](unsigned off, int st, int n0, int k0) -> unsigned {
        int r = n0 + (lane & 7) + ((lane >> 4) & 1) * 8;
        int c = k0 + ((lane >> 3) & 1) * 8;
        return sb + off + (unsigned)((r * st + c) * 2);
    };
    auto adrBt = [&](unsigned off, int st, int k0, int d0) -> unsigned {
        int r = k0 + (lane & 7) + ((lane >> 3) & 1) * 8;
        int c = d0 + ((lane >> 4) & 1) * 8;
        return sb + off + (unsigned)((r * st + c) * 2);
    };

    // =========== Phase A: accA = seq(16 rows) @ w^T (all 256 m) ===========
    float accA[32][4];
    #pragma unroll
    for (int j = 0; j < 32; j++)
        #pragma unroll
        for (int q = 0; q < 4; q++) accA[j][q] = 0.0f;

    for (int kc = 0; kc < 16; kc++) {
        uint4 ph0, ph1, pl0, pl1;
        if (kc < 15) {
            const uint4* gh = (const uint4*)(g_wh) + ((kc + 1) * 256 + t) * 2;
            const uint4* gl = (const uint4*)(g_wl) + ((kc + 1) * 256 + t) * 2;
            ph0 = gh[0]; ph1 = gh[1]; pl0 = gl[0]; pl1 = gl[1];
        }
        unsigned ah0, ah1, ah2, ah3, am0, am1, am2, am3;
        ldsm4(adrA(OFF_SEQ_H, SEQ_ST, wi * 16, kc * 16), ah0, ah1, ah2, ah3);
        ldsm4(adrA(OFF_SEQ_L, SEQ_ST, wi * 16, kc * 16), am0, am1, am2, am3);
        unsigned bufH = OFF_WBUF + (unsigned)(kc & 1) * 24576;
        unsigned bufL = bufH + 12288;
        #pragma unroll
        for (int p = 0; p < 16; p++) {
            unsigned bh0, bh1, bh2, bh3, bl0, bl1, bl2, bl3;
            ldsm4(adrB(bufH, WB_ST, p * 16, 0), bh0, bh1, bh2, bh3);
            ldsm4(adrB(bufL, WB_ST, p * 16, 0), bl0, bl1, bl2, bl3);
            mma16816(accA[2*p],   ah0, ah1, ah2, ah3, bh0, bh1);
            mma16816(accA[2*p],   ah0, ah1, ah2, ah3, bl0, bl1);
            mma16816(accA[2*p],   am0, am1, am2, am3, bh0, bh1);
            mma16816(accA[2*p+1], ah0, ah1, ah2, ah3, bh2, bh3);
            mma16816(accA[2*p+1], ah0, ah1, ah2, ah3, bl2, bl3);
            mma16816(accA[2*p+1], am0, am1, am2, am3, bh2, bh3);
        }
        if (kc < 15) {
            unsigned nb = OFF_WBUF + (unsigned)((kc + 1) & 1) * 24576;
            char* bh = smc + nb + t * 48;
            char* bl = smc + nb + 12288 + t * 48;
            *(uint4*)bh = ph0; *(uint4*)(bh + 16) = ph1;
            *(uint4*)bl = pl0; *(uint4*)(bl + 16) = pl1;
            __syncthreads();
        }
    }

    // ===== epilogue A: bias + tanh, pack to phase-B A-frags (hi/lo) =====
    unsigned pAh[64], pAl[64];
    #pragma unroll
    for (int j = 0; j < 32; j++) {
        float b0 = bias[8 * j + tg * 2], b1 = bias[8 * j + tg * 2 + 1];
        float v0 = tanhf(accA[j][0] + b0), v1 = tanhf(accA[j][1] + b1);
        float v2 = tanhf(accA[j][2] + b0), v3 = tanhf(accA[j][3] + b1);
        int base = (j >> 1) * 4 + (j & 1) * 2;
        pAh[base]     = packhi(v0, v1);
        pAl[base]     = packlo(v0, v1, pAh[base]);
        pAh[base + 1] = packhi(v2, v3);
        pAl[base + 1] = packlo(v2, v3, pAh[base + 1]);
    }

    // =========== Phase B: scores(16 rows x 128 k) = trsf @ seq^T ==========
    float accB[16][4];
    #pragma unroll
    for (int j = 0; j < 16; j++)
        #pragma unroll
        for (int q = 0; q < 4; q++) accB[j][q] = 0.0f;

    #pragma unroll
    for (int kc = 0; kc < 16; kc++) {
        #pragma unroll
        for (int p = 0; p < 8; p++) {
            unsigned bh0, bh1, bh2, bh3, bl0, bl1, bl2, bl3;
            ldsm4(adrB(OFF_SEQ_H, SEQ_ST, p * 16, kc * 16), bh0, bh1, bh2, bh3);
            ldsm4(adrB(OFF_SEQ_L, SEQ_ST, p * 16, kc * 16), bl0, bl1, bl2, bl3);
            mma16816(accB[2*p],   pAh[kc*4], pAh[kc*4+1], pAh[kc*4+2], pAh[kc*4+3], bh0, bh1);
            mma16816(accB[2*p],   pAh[kc*4], pAh[kc*4+1], pAh[kc*4+2], pAh[kc*4+3], bl0, bl1);
            mma16816(accB[2*p],   pAl[kc*4], pAl[kc*4+1], pAl[kc*4+2], pAl[kc*4+3], bh0, bh1);
            mma16816(accB[2*p+1], pAh[kc*4], pAh[kc*4+1], pAh[kc*4+2], pAh[kc*4+3], bh2, bh3);
            mma16816(accB[2*p+1], pAh[kc*4], pAh[kc*4+1], pAh[kc*4+2], pAh[kc*4+3], bl2, bl3);
            mma16816(accB[2*p+1], pAl[kc*4], pAl[kc*4+1], pAl[kc*4+2], pAl[kc*4+3], bh2, bh3);
        }
    }

    // ===== mask add + in-register softmax (rows rg and rg+8) =====
    {
        int l0 = wi * 16 + rg;
        const float* mr0 = maskp + ((size_t)(bb * S_ + e * SEG_ + l0)) * S_
                                 + (size_t)e * SEG_;
        const float* mr1 = mr0 + (size_t)8 * S_;
        #pragma unroll
        for (int j = 0; j < 16; j++) {
            float2 m0 = *(const float2*)(mr0 + 8 * j + tg * 2);
            float2 m1 = *(const float2*)(mr1 + 8 * j + tg * 2);
            if (fixe && l0 == 0) { m0.x = 0.0f; m0.y = 0.0f; }
            accB[j][0] += m0.x; accB[j][1] += m0.y;
            accB[j][2] += m1.x; accB[j][3] += m1.y;
        }
        float mx0 = -3.4e38f, mx1 = -3.4e38f;
        #pragma unroll
        for (int j = 0; j < 16; j++) {
            mx0 = fmaxf(mx0, fmaxf(accB[j][0], accB[j][1]));
            mx1 = fmaxf(mx1, fmaxf(accB[j][2], accB[j][3]));
        }
        mx0 = fmaxf(mx0, __shfl_xor_sync(0xffffffffu, mx0, 1));
        mx0 = fmaxf(mx0, __shfl_xor_sync(0xffffffffu, mx0, 2));
        mx1 = fmaxf(mx1, __shfl_xor_sync(0xffffffffu, mx1, 1));
        mx1 = fmaxf(mx1, __shfl_xor_sync(0xffffffffu, mx1, 2));
        float s0 = 0.0f, s1 = 0.0f;
        #pragma unroll
        for (int j = 0; j < 16; j++) {
            accB[j][0] = expf(accB[j][0] - mx0);
            accB[j][1] = expf(accB[j][1] - mx0);
            accB[j][2] = expf(accB[j][2] - mx1);
            accB[j][3] = expf(accB[j][3] - mx1);
            s0 += accB[j][0] + accB[j][1];
            s1 += accB[j][2] + accB[j][3];
        }
        s0 += __shfl_xor_sync(0xffffffffu, s0, 1);
        s0 += __shfl_xor_sync(0xffffffffu, s0, 2);
        s1 += __shfl_xor_sync(0xffffffffu, s1, 1);
        s1 += __shfl_xor_sync(0xffffffffu, s1, 2);
        float i0 = 1.0f / s0, i1 = 1.0f / s1;
        #pragma unroll
        for (int j = 0; j < 16; j++) {
            accB[j][0] *= i0; accB[j][1] *= i0;
            accB[j][2] *= i1; accB[j][3] *= i1;
        }
    }

    // pack attn to phase-C A-frags
    unsigned aCh[32], aCl[32];
    #pragma unroll
    for (int j = 0; j < 16; j++) {
        int base = (j >> 1) * 4 + (j & 1) * 2;
        aCh[base]     = packhi(accB[j][0], accB[j][1]);
        aCl[base]     = packlo(accB[j][0], accB[j][1], aCh[base]);
        aCh[base + 1] = packhi(accB[j][2], accB[j][3]);
        aCl[base + 1] = packlo(accB[j][2], accB[j][3], aCh[base + 1]);
    }

    // =========== Phase C: ctx(16 rows x 256 d) = attn @ seq, pooled =======
    #pragma unroll
    for (int half = 0; half < 2; half++) {
        float accC[16][4];
        #pragma unroll
        for (int j = 0; j < 16; j++)
            #pragma unroll
            for (int q = 0; q < 4; q++) accC[j][q] = 0.0f;

        #pragma unroll
        for (int kc = 0; kc < 8; kc++) {
            #pragma unroll
            for (int p = 0; p < 8; p++) {
                unsigned bh0, bh1, bh2, bh3, bl0, bl1, bl2, bl3;
                ldsm4t(adrBt(OFF_SEQ_H, SEQ_ST, kc * 16, half * 128 + p * 16),
                       bh0, bh1, bh2, bh3);
                ldsm4t(adrBt(OFF_SEQ_L, SEQ_ST, kc * 16, half * 128 + p * 16),
                       bl0, bl1, bl2, bl3);
                mma16816(accC[2*p],   aCh[kc*4], aCh[kc*4+1], aCh[kc*4+2], aCh[kc*4+3], bh0, bh1);
                mma16816(accC[2*p],   aCh[kc*4], aCh[kc*4+1], aCh[kc*4+2], aCh[kc*4+3], bl0, bl1);
                mma16816(accC[2*p],   aCl[kc*4], aCl[kc*4+1], aCl[kc*4+2], aCl[kc*4+3], bh0, bh1);
                mma16816(accC[2*p+1], aCh[kc*4], aCh[kc*4+1], aCh[kc*4+2], aCh[kc*4+3], bh2, bh3);
                mma16816(accC[2*p+1], aCh[kc*4], aCh[kc*4+1], aCh[kc*4+2], aCh[kc*4+3], bl2, bl3);
                mma16816(accC[2*p+1], aCl[kc*4], aCl[kc*4+1], aCl[kc*4+2], aCl[kc*4+3], bh2, bh3);
            }
        }
        // pool over the warp's 16 rows, write per-warp result
        #pragma unroll
        for (int j = 0; j < 16; j++) {
            float m0 = fmaxf(accC[j][0], accC[j][2]);
            float m1 = fmaxf(accC[j][1], accC[j][3]);
            m0 = fmaxf(m0, __shfl_xor_sync(0xffffffffu, m0, 4));
            m0 = fmaxf(m0, __shfl_xor_sync(0xffffffffu, m0, 8));
            m0 = fmaxf(m0, __shfl_xor_sync(0xffffffffu, m0, 16));
            m1 = fmaxf(m1, __shfl_xor_sync(0xffffffffu, m1, 4));
            m1 = fmaxf(m1, __shfl_xor_sync(0xffffffffu, m1, 8));
            m1 = fmaxf(m1, __shfl_xor_sync(0xffffffffu, m1, 16));
            if (rg == 0) {
                int d = half * 128 + 8 * j + tg * 2;
                pool[wi * 256 + d]     = m0;
                pool[wi * 256 + d + 1] = m1;
            }
        }
    }
    __syncthreads();

    // ---- final pool reduce over 8 warps ----
    {
        float mx = -3.4e38f;
        #pragma unroll
        for (int w = 0; w < 8; w++) mx = fmaxf(mx, pool[w * 256 + t]);
        out[((size_t)bb * E_ + e) * D_ + t] = mx;
    }

    // new_mask[b][e][s] = (s/128 == e)
    float* nm = out + (size_t)B_ * E_ * D_ + ((size_t)bb * E_ + e) * S_;
    for (int s = t; s < S_; s += 256)
        nm[s] = ((s >> 7) == e) ? 1.0f : 0.0f;
}

// ---------------------------------------------------------------------------
extern "C" void kernel_launch(void* const* d_in, const int* in_sizes, int n_in,
                              void* d_out, int out_size) {
    const float* hidden = (const float*)d_in[0];
    const float* mask   = (const float*)d_in[1];
    const float* w      = (const float*)d_in[2];
    const float* bvec   = (const float*)d_in[3];
    float* out = (float*)d_out;
    (void)in_sizes; (void)n_in; (void)out_size;

    prep_kernel<<<256, 256>>>(w);
    fix_kernel<<<E_, 256>>>(mask);

    cudaFuncSetAttribute(main_kernel,
                         cudaFuncAttributeMaxDynamicSharedMemorySize, SMEM_TOT);
    main_kernel<<<dim3(E_, B_), 256, SMEM_TOT>>>(hidden, mask, bvec, out);
}

// round 8
// speedup vs baseline: 1.3126x; 1.3126x over previous
#include <cuda_runtime.h>
#include <cuda_bf16.h>
#include <math.h>
#include <stdint.h>

#define B_   8
#define S_   4096
#define D_   256
#define SEG_ 128
#define E_   32
#define MASKVAL (-3.402823466e38f)

#define SEQ_ST 264   // halves
#define WB_ST  24    // halves
#define TRS_ST 264   // halves

// smem byte offsets
#define OFF_SEQ_H 0                 // 128*264*2 = 67584
#define OFF_SEQ_L 67584             // 67584
#define OFF_WBUF  135168            // 2 bufs x 12288 (6144 hi + 6144 lo)
#define OFF_TRSLO 159744            // 8 warps x 8448 (16 rows x 264 halves)
#define OFF_BIAS  227328            // 1024
#define OFF_POOL  OFF_WBUF          // alias (w dead after phase A)
#define SMEM_TOT  228352

// w packed per chunk cc = half*16 + kc: [cc][m 0..127][kk 0..15 pad 24]
__device__ __nv_bfloat16 g_wh[32 * 3072];
__device__ __nv_bfloat16 g_wl[32 * 3072];
__device__ int g_fix[E_];

// ---------------------------------------------------------------------------
// merged prep (w pack+split) + fix (mask scan). grid = E_, block = 256.
// ---------------------------------------------------------------------------
__global__ void prep_fix_kernel(const float* __restrict__ w,
                                const float* __restrict__ mask) {
    int e = blockIdx.x, t = threadIdx.x;
    #pragma unroll
    for (int i = 0; i < 8; i++) {
        int idx = (e * 256 + t) + i * 8192;       // 65536 total
        int m = idx >> 8, d = idx & 255;
        float v = w[idx];
        __nv_bfloat16 h = __float2bfloat16(v);
        __nv_bfloat16 l = __float2bfloat16(v - __bfloat162float(h));
        int half = m >> 7, mloc = m & 127, kc = d >> 4, kk = d & 15;
        int off = ((half * 16 + kc) * 128 + mloc) * 24 + kk;
        g_wh[off] = h; g_wl[off] = l;
    }
    if (t == 0) g_fix[e] = 0;
    __syncthreads();

    int warp = t >> 5, lane = t & 31;
    int found = 0;
    for (int r = warp; r < B_ * SEG_; r += 8) {
        int b = r >> 7, l = r & 127;
        const float* row = mask + ((size_t)b * S_ + (size_t)e * SEG_ + l) * S_
                                + (size_t)e * SEG_;
        int allm = 1;
        #pragma unroll
        for (int k = 0; k < 4; k++)
            if (row[lane + 32 * k] != MASKVAL) allm = 0;
        if (__all_sync(0xffffffffu, allm)) { found = 1; break; }
    }
    if (found && lane == 0) atomicOr(&g_fix[e], 1);
}

// ---------------------------------------------------------------------------
__device__ __forceinline__ void ldsm4(unsigned a, unsigned& r0, unsigned& r1,
                                      unsigned& r2, unsigned& r3) {
    asm volatile("ldmatrix.sync.aligned.m8n8.x4.shared.b16 {%0,%1,%2,%3},[%4];"
                 : "=r"(r0), "=r"(r1), "=r"(r2), "=r"(r3) : "r"(a));
}
__device__ __forceinline__ void ldsm4t(unsigned a, unsigned& r0, unsigned& r1,
                                       unsigned& r2, unsigned& r3) {
    asm volatile("ldmatrix.sync.aligned.m8n8.x4.trans.shared.b16 {%0,%1,%2,%3},[%4];"
                 : "=r"(r0), "=r"(r1), "=r"(r2), "=r"(r3) : "r"(a));
}
__device__ __forceinline__ void mma16816(float* c, unsigned a0, unsigned a1,
                                         unsigned a2, unsigned a3,
                                         unsigned b0, unsigned b1) {
    asm volatile(
        "mma.sync.aligned.m16n8k16.row.col.f32.bf16.bf16.f32 "
        "{%0,%1,%2,%3},{%4,%5,%6,%7},{%8,%9},{%0,%1,%2,%3};"
        : "+f"(c[0]), "+f"(c[1]), "+f"(c[2]), "+f"(c[3])
        : "r"(a0), "r"(a1), "r"(a2), "r"(a3), "r"(b0), "r"(b1));
}
__device__ __forceinline__ unsigned packhi(float a, float b) {
    __nv_bfloat162 p;
    p.x = __float2bfloat16(a); p.y = __float2bfloat16(b);
    return *(unsigned*)&p;
}
__device__ __forceinline__ unsigned packlo(float a, float b, unsigned hi) {
    __nv_bfloat162 h = *(__nv_bfloat162*)&hi;
    __nv_bfloat162 p;
    p.x = __float2bfloat16(a - __bfloat162float(h.x));
    p.y = __float2bfloat16(b - __bfloat162float(h.y));
    return *(unsigned*)&p;
}

// ---------------------------------------------------------------------------
__global__ void __launch_bounds__(256)
main_kernel(const float* __restrict__ hidden,
            const float* __restrict__ maskp,
            const float* __restrict__ bvec,
            float* __restrict__ out)
{
    extern __shared__ char smc[];
    const unsigned sb = (unsigned)__cvta_generic_to_shared(smc);

    __nv_bfloat16* seqh = (__nv_bfloat16*)(smc + OFF_SEQ_H);
    __nv_bfloat16* seql = (__nv_bfloat16*)(smc + OFF_SEQ_L);
    float* bias = (float*)(smc + OFF_BIAS);
    float* pool = (float*)(smc + OFF_POOL);

    const int t = threadIdx.x;
    const int lane = t & 31, wi = t >> 5;
    const int rg = lane >> 2, tg = lane & 3;
    const int e = blockIdx.x, bb = blockIdx.y;

    // ---- load seq tile, split bf16 hi/lo ----
    const float* seq_g = hidden + ((size_t)bb * S_ + (size_t)e * SEG_) * D_;
    for (int i = t; i < SEG_ * D_ / 4; i += 256) {
        int l = i >> 6, d = (i & 63) << 2;
        float4 v = *(const float4*)(seq_g + l * D_ + d);
        __nv_bfloat162 h0, h1, l0, l1;
        h0.x = __float2bfloat16(v.x); h0.y = __float2bfloat16(v.y);
        h1.x = __float2bfloat16(v.z); h1.y = __float2bfloat16(v.w);
        l0.x = __float2bfloat16(v.x - __bfloat162float(h0.x));
        l0.y = __float2bfloat16(v.y - __bfloat162float(h0.y));
        l1.x = __float2bfloat16(v.z - __bfloat162float(h1.x));
        l1.y = __float2bfloat16(v.w - __bfloat162float(h1.y));
        *(__nv_bfloat162*)(seqh + l * SEQ_ST + d)     = h0;
        *(__nv_bfloat162*)(seqh + l * SEQ_ST + d + 2) = h1;
        *(__nv_bfloat162*)(seql + l * SEQ_ST + d)     = l0;
        *(__nv_bfloat162*)(seql + l * SEQ_ST + d + 2) = l1;
    }
    bias[t] = bvec[t];
    const int fixe = g_fix[e];

    // ---- w chunk fetch/store helpers (chunk = 384 uint4 hi + 384 uint4 lo)
    uint4 fA, fB, fC, fD;
    auto fetch = [&](int cc) {
        const uint4* gh = (const uint4*)g_wh + cc * 384;
        const uint4* gl = (const uint4*)g_wl + cc * 384;
        fA = gh[t]; fC = gl[t];
        if (t < 128) { fB = gh[256 + t]; fD = gl[256 + t]; }
    };
    auto wstore = [&](int bufi) {
        unsigned base = OFF_WBUF + (unsigned)bufi * 12288;
        *(uint4*)(smc + base + t * 16) = fA;
        *(uint4*)(smc + base + 6144 + t * 16) = fC;
        if (t < 128) {
            *(uint4*)(smc + base + 4096 + t * 16) = fB;
            *(uint4*)(smc + base + 6144 + 4096 + t * 16) = fD;
        }
    };

    // ldmatrix address helpers (validated maps)
    auto adrA = [&](unsigned off, int st, int r0, int k0) -> unsigned {
        int r = r0 + (lane & 7) + ((lane >> 3) & 1) * 8;
        int c = k0 + ((lane >> 4) & 1) * 8;
        return sb + off + (unsigned)((r * st + c) * 2);
    };
    auto adrB = [&](unsigned off, int st, int n0, int k0) -> unsigned {
        int r = n0 + (lane & 7) + ((lane >> 4) & 1) * 8;
        int c = k0 + ((lane >> 3) & 1) * 8;
        return sb + off + (unsigned)((r * st + c) * 2);
    };
    auto adrBt = [&](unsigned off, int st, int k0, int d0) -> unsigned {
        int r = k0 + (lane & 7) + ((lane >> 3) & 1) * 8;
        int c = d0 + ((lane >> 4) & 1) * 8;
        return sb + off + (unsigned)((r * st + c) * 2);
    };

    fetch(0);
    __syncthreads();     // seq smem ready
    wstore(0);
    __syncthreads();

    // =========== Phase A: trsf = tanh(seq @ w^T + b), two m-halves ========
    unsigned pAh[64];                       // trsf hi A-frags (all 256 m)
    const unsigned trsloW = OFF_TRSLO + (unsigned)wi * 8448;

    for (int h = 0; h < 2; h++) {
        float accA[16][4];
        #pragma unroll
        for (int j = 0; j < 16; j++)
            #pragma unroll
            for (int q = 0; q < 4; q++) accA[j][q] = 0.0f;

        for (int kc = 0; kc < 16; kc++) {
            int cc = h * 16 + kc;
            if (cc < 31) fetch(cc + 1);
            unsigned ah0, ah1, ah2, ah3, am0, am1, am2, am3;
            ldsm4(adrA(OFF_SEQ_H, SEQ_ST, wi * 16, kc * 16), ah0, ah1, ah2, ah3);
            ldsm4(adrA(OFF_SEQ_L, SEQ_ST, wi * 16, kc * 16), am0, am1, am2, am3);
            unsigned bufH = OFF_WBUF + (unsigned)(cc & 1) * 12288;
            unsigned bufL = bufH + 6144;
            #pragma unroll
            for (int p = 0; p < 8; p++) {
                unsigned bh0, bh1, bh2, bh3, bl0, bl1, bl2, bl3;
                ldsm4(adrB(bufH, WB_ST, p * 16, 0), bh0, bh1, bh2, bh3);
                ldsm4(adrB(bufL, WB_ST, p * 16, 0), bl0, bl1, bl2, bl3);
                mma16816(accA[2*p],   ah0, ah1, ah2, ah3, bh0, bh1);
                mma16816(accA[2*p],   ah0, ah1, ah2, ah3, bl0, bl1);
                mma16816(accA[2*p],   am0, am1, am2, am3, bh0, bh1);
                mma16816(accA[2*p+1], ah0, ah1, ah2, ah3, bh2, bh3);
                mma16816(accA[2*p+1], ah0, ah1, ah2, ah3, bl2, bl3);
                mma16816(accA[2*p+1], am0, am1, am2, am3, bh2, bh3);
            }
            if (cc < 31) wstore((cc + 1) & 1);
            __syncthreads();
        }

        // epilogue: bias + tanh; hi frags -> regs, lo split -> warp smem
        #pragma unroll
        for (int j = 0; j < 16; j++) {
            int jg = h * 16 + j;
            float b0 = bias[8 * jg + tg * 2], b1 = bias[8 * jg + tg * 2 + 1];
            float v0 = tanhf(accA[j][0] + b0), v1 = tanhf(accA[j][1] + b1);
            float v2 = tanhf(accA[j][2] + b0), v3 = tanhf(accA[j][3] + b1);
            int base = (jg >> 1) * 4 + (jg & 1) * 2;
            pAh[base]     = packhi(v0, v1);
            pAh[base + 1] = packhi(v2, v3);
            unsigned lo01 = packlo(v0, v1, pAh[base]);
            unsigned lo23 = packlo(v2, v3, pAh[base + 1]);
            int m0 = 8 * jg + tg * 2;
            *(unsigned*)(smc + trsloW + (unsigned)((rg * TRS_ST + m0) * 2)) = lo01;
            *(unsigned*)(smc + trsloW + (unsigned)(((rg + 8) * TRS_ST + m0) * 2)) = lo23;
        }
    }
    __syncwarp();   // warp-private trslo writes -> ldsm reads below

    // =========== Phase B: scores(16 rows x 128 k) = trsf @ seq^T ==========
    float accB[16][4];
    #pragma unroll
    for (int j = 0; j < 16; j++)
        #pragma unroll
        for (int q = 0; q < 4; q++) accB[j][q] = 0.0f;

    #pragma unroll
    for (int kc = 0; kc < 16; kc++) {
        unsigned Al0, Al1, Al2, Al3;
        ldsm4(adrA(OFF_TRSLO + wi * 8448, TRS_ST, 0, kc * 16), Al0, Al1, Al2, Al3);
        #pragma unroll
        for (int p = 0; p < 8; p++) {
            unsigned bh0, bh1, bh2, bh3, bl0, bl1, bl2, bl3;
            ldsm4(adrB(OFF_SEQ_H, SEQ_ST, p * 16, kc * 16), bh0, bh1, bh2, bh3);
            ldsm4(adrB(OFF_SEQ_L, SEQ_ST, p * 16, kc * 16), bl0, bl1, bl2, bl3);
            mma16816(accB[2*p],   pAh[kc*4], pAh[kc*4+1], pAh[kc*4+2], pAh[kc*4+3], bh0, bh1);
            mma16816(accB[2*p],   pAh[kc*4], pAh[kc*4+1], pAh[kc*4+2], pAh[kc*4+3], bl0, bl1);
            mma16816(accB[2*p],   Al0, Al1, Al2, Al3, bh0, bh1);
            mma16816(accB[2*p+1], pAh[kc*4], pAh[kc*4+1], pAh[kc*4+2], pAh[kc*4+3], bh2, bh3);
            mma16816(accB[2*p+1], pAh[kc*4], pAh[kc*4+1], pAh[kc*4+2], pAh[kc*4+3], bl2, bl3);
            mma16816(accB[2*p+1], Al0, Al1, Al2, Al3, bh2, bh3);
        }
    }

    // ===== mask add + in-register softmax (rows rg and rg+8) =====
    {
        int l0 = wi * 16 + rg;
        const float* mr0 = maskp + ((size_t)(bb * S_ + e * SEG_ + l0)) * S_
                                 + (size_t)e * SEG_;
        const float* mr1 = mr0 + (size_t)8 * S_;
        #pragma unroll
        for (int j = 0; j < 16; j++) {
            float2 m0 = *(const float2*)(mr0 + 8 * j + tg * 2);
            float2 m1 = *(const float2*)(mr1 + 8 * j + tg * 2);
            if (fixe && l0 == 0) { m0.x = 0.0f; m0.y = 0.0f; }
            accB[j][0] += m0.x; accB[j][1] += m0.y;
            accB[j][2] += m1.x; accB[j][3] += m1.y;
        }
        float mx0 = -3.4e38f, mx1 = -3.4e38f;
        #pragma unroll
        for (int j = 0; j < 16; j++) {
            mx0 = fmaxf(mx0, fmaxf(accB[j][0], accB[j][1]));
            mx1 = fmaxf(mx1, fmaxf(accB[j][2], accB[j][3]));
        }
        mx0 = fmaxf(mx0, __shfl_xor_sync(0xffffffffu, mx0, 1));
        mx0 = fmaxf(mx0, __shfl_xor_sync(0xffffffffu, mx0, 2));
        mx1 = fmaxf(mx1, __shfl_xor_sync(0xffffffffu, mx1, 1));
        mx1 = fmaxf(mx1, __shfl_xor_sync(0xffffffffu, mx1, 2));
        float s0 = 0.0f, s1 = 0.0f;
        #pragma unroll
        for (int j = 0; j < 16; j++) {
            accB[j][0] = expf(accB[j][0] - mx0);
            accB[j][1] = expf(accB[j][1] - mx0);
            accB[j][2] = expf(accB[j][2] - mx1);
            accB[j][3] = expf(accB[j][3] - mx1);
            s0 += accB[j][0] + accB[j][1];
            s1 += accB[j][2] + accB[j][3];
        }
        s0 += __shfl_xor_sync(0xffffffffu, s0, 1);
        s0 += __shfl_xor_sync(0xffffffffu, s0, 2);
        s1 += __shfl_xor_sync(0xffffffffu, s1, 1);
        s1 += __shfl_xor_sync(0xffffffffu, s1, 2);
        float i0 = 1.0f / s0, i1 = 1.0f / s1;
        #pragma unroll
        for (int j = 0; j < 16; j++) {
            accB[j][0] *= i0; accB[j][1] *= i0;
            accB[j][2] *= i1; accB[j][3] *= i1;
        }
    }

    // pack attn to phase-C A-frags
    unsigned aCh[32], aCl[32];
    #pragma unroll
    for (int j = 0; j < 16; j++) {
        int base = (j >> 1) * 4 + (j & 1) * 2;
        aCh[base]     = packhi(accB[j][0], accB[j][1]);
        aCl[base]     = packlo(accB[j][0], accB[j][1], aCh[base]);
        aCh[base + 1] = packhi(accB[j][2], accB[j][3]);
        aCl[base + 1] = packlo(accB[j][2], accB[j][3], aCh[base + 1]);
    }

    // =========== Phase C: ctx(16 rows x 256 d) = attn @ seq, pooled =======
    #pragma unroll
    for (int half = 0; half < 2; half++) {
        float accC[16][4];
        #pragma unroll
        for (int j = 0; j < 16; j++)
            #pragma unroll
            for (int q = 0; q < 4; q++) accC[j][q] = 0.0f;

        #pragma unroll
        for (int kc = 0; kc < 8; kc++) {
            #pragma unroll
            for (int p = 0; p < 8; p++) {
                unsigned bh0, bh1, bh2, bh3, bl0, bl1, bl2, bl3;
                ldsm4t(adrBt(OFF_SEQ_H, SEQ_ST, kc * 16, half * 128 + p * 16),
                       bh0, bh1, bh2, bh3);
                ldsm4t(adrBt(OFF_SEQ_L, SEQ_ST, kc * 16, half * 128 + p * 16),
                       bl0, bl1, bl2, bl3);
                mma16816(accC[2*p],   aCh[kc*4], aCh[kc*4+1], aCh[kc*4+2], aCh[kc*4+3], bh0, bh1);
                mma16816(accC[2*p],   aCh[kc*4], aCh[kc*4+1], aCh[kc*4+2], aCh[kc*4+3], bl0, bl1);
                mma16816(accC[2*p],   aCl[kc*4], aCl[kc*4+1], aCl[kc*4+2], aCl[kc*4+3], bh0, bh1);
                mma16816(accC[2*p+1], aCh[kc*4], aCh[kc*4+1], aCh[kc*4+2], aCh[kc*4+3], bh2, bh3);
                mma16816(accC[2*p+1], aCh[kc*4], aCh[kc*4+1], aCh[kc*4+2], aCh[kc*4+3], bl2, bl3);
                mma16816(accC[2*p+1], aCl[kc*4], aCl[kc*4+1], aCl[kc*4+2], aCl[kc*4+3], bh2, bh3);
            }
        }
        #pragma unroll
        for (int j = 0; j < 16; j++) {
            float m0 = fmaxf(accC[j][0], accC[j][2]);
            float m1 = fmaxf(accC[j][1], accC[j][3]);
            m0 = fmaxf(m0, __shfl_xor_sync(0xffffffffu, m0, 4));
            m0 = fmaxf(m0, __shfl_xor_sync(0xffffffffu, m0, 8));
            m0 = fmaxf(m0, __shfl_xor_sync(0xffffffffu, m0, 16));
            m1 = fmaxf(m1, __shfl_xor_sync(0xffffffffu, m1, 4));
            m1 = fmaxf(m1, __shfl_xor_sync(0xffffffffu, m1, 8));
            m1 = fmaxf(m1, __shfl_xor_sync(0xffffffffu, m1, 16));
            if (rg == 0) {
                int d = half * 128 + 8 * j + tg * 2;
                pool[wi * 256 + d]     = m0;
                pool[wi * 256 + d + 1] = m1;
            }
        }
    }
    __syncthreads();

    // ---- final pool reduce over 8 warps ----
    {
        float mx = -3.4e38f;
        #pragma unroll
        for (int w = 0; w < 8; w++) mx = fmaxf(mx, pool[w * 256 + t]);
        out[((size_t)bb * E_ + e) * D_ + t] = mx;
    }

    // new_mask[b][e][s] = (s/128 == e)
    float* nm = out + (size_t)B_ * E_ * D_ + ((size_t)bb * E_ + e) * S_;
    for (int s = t; s < S_; s += 256)
        nm[s] = ((s >> 7) == e) ? 1.0f : 0.0f;
}

// ---------------------------------------------------------------------------
extern "C" void kernel_launch(void* const* d_in, const int* in_sizes, int n_in,
                              void* d_out, int out_size) {
    const float* hidden = (const float*)d_in[0];
    const float* mask   = (const float*)d_in[1];
    const float* w      = (const float*)d_in[2];
    const float* bvec   = (const float*)d_in[3];
    float* out = (float*)d_out;
    (void)in_sizes; (void)n_in; (void)out_size;

    prep_fix_kernel<<<E_, 256>>>(w, mask);

    cudaFuncSetAttribute(main_kernel,
                         cudaFuncAttributeMaxDynamicSharedMemorySize, SMEM_TOT);
    main_kernel<<<dim3(E_, B_), 256, SMEM_TOT>>>(hidden, mask, bvec, out);
}